// round 7
// baseline (speedup 1.0000x reference)
#include <cuda_runtime.h>
#include <cuda_bf16.h>
#include <cstdint>
#include <cstddef>

// ============================================================================
// KMeansLoss on GB300 via legacy mma.sync — harness ptxas target is sm_103
// (no 'a'); tcgen05 unavailable. R7: cross-term GEMM in FP8 e4m3 m16n8k32
// (halves legacy-MMA instruction count vs bf16 k16 — the R2..R6 plateau at
// tensor~45% across three schedules shows the legacy MMA issue rate is the
// binding constraint). xsq/csq remain exact fp32, so only the 2*x.c term is
// quantized.
//
// loss = ALPHA * mean_n sqrt(max( xsq[n] + min_k( csq[k] - 2*dot(x_n,c_k) ), 0))
//
// Kernel 0 (64 CTAs x 32 thr): centers fp32 -> e4m3 fragment order + exact csq.
// Kernel 1 (512 CTAs x 128 thr, 3 CTAs/SM): warp owns 32 rows (2 m16 tiles);
//   A fragments direct gmem->regs (64 regs fp8) + exact fp32 xsq in regs.
//   B streamed via 6-stage mbarrier pipeline (8KB stages, produce distance 3,
//   cp.async.mbarrier.arrive.noinc), zero mainloop __syncthreads.
//   8 independent QMMA chains per ks. Fold (csq - 2*dot) into per-row min.
//   Deterministic last-CTA reduction -> scalar.
// ============================================================================

namespace km {

constexpr int BATCH = 65536;
constexpr int KC    = 512;
constexpr int DIM   = 256;
constexpr float ALPHA = 0.05f;

constexpr int M_CTA    = 128;
constexpr int NUM_CTAS = BATCH / M_CTA;     // 512
constexpr int NCH      = 32;                // centers per chunk
constexpr int NCHUNKS  = KC / NCH;          // 16
constexpr int KSTEPS   = DIM / 32;          // 8 k-steps of 32 (fp8 k32)
constexpr int CHUNK_BYTES = NCH * DIM;      // 8192 (fp8)
constexpr int NSTAGE   = 6;
constexpr int PDIST    = 3;

// ---- dynamic smem layout ----
constexpr int SM_CSQ  = 0;                  // 512 f = 2048 B
constexpr int SM_RED  = 2048;               // 4 f
constexpr int SM_MBF  = 2112;               // full mbars, 6 x 8B
constexpr int SM_MBE  = 2176;               // empty mbars, 6 x 8B
constexpr int SM_BB   = 4096;               // 6 x 8 KB B stages
constexpr int SMEM_TOTAL = SM_BB + NSTAGE * CHUNK_BYTES;   // 53248

// B fragments: [nbg(64)][ks(8)][lane(32)] x uint2
//   b0 = col g, k = ks*32 + 4t..4t+3 ; b1 = col g, k = ks*32 + 16 + 4t..4t+3
__device__ uint2 g_Bfrag[(KC / 8) * KSTEPS * 32];
__device__ float g_csq[KC];
__device__ float g_partials[NUM_CTAS];
__device__ unsigned int g_done;

// ---------------------------- helpers ---------------------------------------
// pack 4 floats -> 4 x e4m3 in one u32 (f0 in lowest byte)
__device__ __forceinline__ uint32_t pk_e4m3x4(float f0, float f1, float f2, float f3) {
    uint32_t r;
    asm("{\n .reg .b16 lo, hi;\n"
        " cvt.rn.satfinite.e4m3x2.f32 lo, %2, %1;\n"
        " cvt.rn.satfinite.e4m3x2.f32 hi, %4, %3;\n"
        " mov.b32 %0, {lo, hi};\n}"
        : "=r"(r) : "f"(f0), "f"(f1), "f"(f2), "f"(f3));
    return r;
}
__device__ __forceinline__ void mma16832(float c[4], const uint32_t a[4],
                                         uint32_t b0, uint32_t b1) {
    asm volatile(
        "mma.sync.aligned.m16n8k32.row.col.f32.e4m3.e4m3.f32 "
        "{%0,%1,%2,%3}, {%4,%5,%6,%7}, {%8,%9}, {%0,%1,%2,%3};"
        : "+f"(c[0]), "+f"(c[1]), "+f"(c[2]), "+f"(c[3])
        : "r"(a[0]), "r"(a[1]), "r"(a[2]), "r"(a[3]), "r"(b0), "r"(b1));
}
__device__ __forceinline__ uint32_t smem_u32(const void* p) {
    return (uint32_t)__cvta_generic_to_shared(p);
}
__device__ __forceinline__ void cp16(uint32_t sdst, const void* gsrc) {
    asm volatile("cp.async.cg.shared.global [%0], [%1], 16;"
                 :: "r"(sdst), "l"(gsrc) : "memory");
}
__device__ __forceinline__ void cp_mbar_arrive_noinc(uint32_t mbar) {
    asm volatile("cp.async.mbarrier.arrive.noinc.shared::cta.b64 [%0];"
                 :: "r"(mbar) : "memory");
}
__device__ __forceinline__ void mbar_init(uint32_t a, uint32_t cnt) {
    asm volatile("mbarrier.init.shared.b64 [%0], %1;" :: "r"(a), "r"(cnt) : "memory");
}
__device__ __forceinline__ void mbar_arrive(uint32_t a) {
    asm volatile("mbarrier.arrive.shared.b64 _, [%0];" :: "r"(a) : "memory");
}
__device__ __forceinline__ void mbar_wait_parity(uint32_t mbar, uint32_t phase) {
    uint32_t done;
    do {
        asm volatile("{\n .reg .pred p;\n"
                     " mbarrier.try_wait.parity.acquire.cta.shared::cta.b64 p, [%1], %2, 0x989680;\n"
                     " selp.b32 %0, 1, 0, p;\n}"
                     : "=r"(done) : "r"(mbar), "r"(phase) : "memory");
    } while (!done);
}

// ------------------------- kernel 0: center convert -------------------------
// one warp per 8-center group; emits fp8 fragment order + exact fp32 csq.
__global__ void __launch_bounds__(32) convert_centers(const float* __restrict__ ctr) {
    const int l   = threadIdx.x & 31;
    const int nbg = blockIdx.x;                 // 0..63
    const int n   = nbg * 8 + (l >> 2);
    const int t   = l & 3;
    const float* row = ctr + (size_t)n * DIM;
    float cs = 0.0f;
    #pragma unroll
    for (int ks = 0; ks < KSTEPS; ++ks) {
        const int k0 = ks * 32 + 4 * t;
        const float4 v0 = *reinterpret_cast<const float4*>(row + k0);
        const float4 v1 = *reinterpret_cast<const float4*>(row + k0 + 16);
        cs = fmaf(v0.x, v0.x, cs); cs = fmaf(v0.y, v0.y, cs);
        cs = fmaf(v0.z, v0.z, cs); cs = fmaf(v0.w, v0.w, cs);
        cs = fmaf(v1.x, v1.x, cs); cs = fmaf(v1.y, v1.y, cs);
        cs = fmaf(v1.z, v1.z, cs); cs = fmaf(v1.w, v1.w, cs);
        uint2 u;
        u.x = pk_e4m3x4(v0.x, v0.y, v0.z, v0.w);
        u.y = pk_e4m3x4(v1.x, v1.y, v1.z, v1.w);
        g_Bfrag[(nbg * KSTEPS + ks) * 32 + l] = u;
    }
    cs += __shfl_xor_sync(0xFFFFFFFFu, cs, 1);
    cs += __shfl_xor_sync(0xFFFFFFFFu, cs, 2);
    if (t == 0) g_csq[n] = cs;
}

// ------------------------- kernel 1: main GEMM+min --------------------------
__global__ void __launch_bounds__(128, 3)
kmeans_main(const float* __restrict__ emb, float* __restrict__ out) {
    extern __shared__ char smem[];
    const int tid = threadIdx.x;
    const int w   = tid >> 5;        // warp 0..3
    const int l   = tid & 31;
    const int t   = l & 3;
    const int m0  = blockIdx.x * M_CTA;
    float* csq_s = reinterpret_cast<float*>(smem + SM_CSQ);
    float* red_s = reinterpret_cast<float*>(smem + SM_RED);
    const uint32_t sbase = smem_u32(smem);

    // ---- init pipeline mbarriers + stage csq in smem ----
    if (tid == 0) {
        #pragma unroll
        for (int s = 0; s < NSTAGE; ++s) {
            mbar_init(sbase + SM_MBF + s * 8, 128);
            mbar_init(sbase + SM_MBE + s * 8, 128);
        }
    }
    reinterpret_cast<float4*>(csq_s)[tid] =
        reinterpret_cast<const float4*>(g_csq)[tid];
    __syncthreads();

    // ---- prefill stages 0..PDIST-1 (4 cp16/thread per 8KB chunk) ----
    #pragma unroll
    for (int s = 0; s < PDIST; ++s) {
        const char* src = reinterpret_cast<const char*>(g_Bfrag) + s * CHUNK_BYTES;
        const uint32_t dst = sbase + SM_BB + s * CHUNK_BYTES;
        #pragma unroll
        for (int i = 0; i < 4; ++i) {
            const int off = (i * 128 + tid) * 16;
            cp16(dst + off, src + off);
        }
        cp_mbar_arrive_noinc(sbase + SM_MBF + s * 8);
    }

    // ---- A prologue: gmem fp32 -> fp8 register fragments, fused exact xsq ----
    // a[mt][ks]: a0 = row g,   k=ks*32+4t..+3 ; a1 = row g+8, same k
    //            a2 = row g,   k+16..+19      ; a3 = row g+8, k+16..+19
    uint32_t a[2][KSTEPS][4];
    float xs[2][2];
    xs[0][0] = 0.0f; xs[0][1] = 0.0f; xs[1][0] = 0.0f; xs[1][1] = 0.0f;
    {
        const float* base = emb + (size_t)(m0 + w * 32 + (l >> 2)) * DIM + 4 * t;
        #pragma unroll
        for (int mt = 0; mt < 2; ++mt) {
            const float* p0 = base + (size_t)(mt * 16) * DIM;
            const float* p8 = p0 + (size_t)8 * DIM;
            #pragma unroll
            for (int ks = 0; ks < KSTEPS; ++ks) {
                const float4 v00 = *reinterpret_cast<const float4*>(p0 + ks * 32);
                const float4 v01 = *reinterpret_cast<const float4*>(p0 + ks * 32 + 16);
                const float4 v10 = *reinterpret_cast<const float4*>(p8 + ks * 32);
                const float4 v11 = *reinterpret_cast<const float4*>(p8 + ks * 32 + 16);
                xs[mt][0] = fmaf(v00.x, v00.x, xs[mt][0]);
                xs[mt][0] = fmaf(v00.y, v00.y, xs[mt][0]);
                xs[mt][0] = fmaf(v00.z, v00.z, xs[mt][0]);
                xs[mt][0] = fmaf(v00.w, v00.w, xs[mt][0]);
                xs[mt][0] = fmaf(v01.x, v01.x, xs[mt][0]);
                xs[mt][0] = fmaf(v01.y, v01.y, xs[mt][0]);
                xs[mt][0] = fmaf(v01.z, v01.z, xs[mt][0]);
                xs[mt][0] = fmaf(v01.w, v01.w, xs[mt][0]);
                xs[mt][1] = fmaf(v10.x, v10.x, xs[mt][1]);
                xs[mt][1] = fmaf(v10.y, v10.y, xs[mt][1]);
                xs[mt][1] = fmaf(v10.z, v10.z, xs[mt][1]);
                xs[mt][1] = fmaf(v10.w, v10.w, xs[mt][1]);
                xs[mt][1] = fmaf(v11.x, v11.x, xs[mt][1]);
                xs[mt][1] = fmaf(v11.y, v11.y, xs[mt][1]);
                xs[mt][1] = fmaf(v11.z, v11.z, xs[mt][1]);
                xs[mt][1] = fmaf(v11.w, v11.w, xs[mt][1]);
                a[mt][ks][0] = pk_e4m3x4(v00.x, v00.y, v00.z, v00.w);
                a[mt][ks][1] = pk_e4m3x4(v10.x, v10.y, v10.z, v10.w);
                a[mt][ks][2] = pk_e4m3x4(v01.x, v01.y, v01.z, v01.w);
                a[mt][ks][3] = pk_e4m3x4(v11.x, v11.y, v11.z, v11.w);
            }
        }
    }
    #pragma unroll
    for (int mt = 0; mt < 2; ++mt) {
        #pragma unroll
        for (int h = 0; h < 2; ++h) {
            xs[mt][h] += __shfl_xor_sync(0xFFFFFFFFu, xs[mt][h], 1);
            xs[mt][h] += __shfl_xor_sync(0xFFFFFFFFu, xs[mt][h], 2);
        }
    }

    float minv[2][2];
    minv[0][0] = 3.4e38f; minv[0][1] = 3.4e38f;
    minv[1][0] = 3.4e38f; minv[1][1] = 3.4e38f;

    // ---- mainloop: 16 chunks, mbarrier pipeline, no __syncthreads ----
    int cst = 0, cph = 0;
    int pst = PDIST, pph = 1;

    #pragma unroll 1
    for (int ck = 0; ck < NCHUNKS; ++ck) {
        mbar_wait_parity(sbase + SM_MBF + cst * 8, (uint32_t)cph);

        const char* bb = smem + SM_BB + cst * CHUNK_BYTES;

        float acc[2][4][4];
        #pragma unroll
        for (int mt = 0; mt < 2; ++mt)
            #pragma unroll
            for (int nb = 0; nb < 4; ++nb)
                #pragma unroll
                for (int c = 0; c < 4; ++c) acc[mt][nb][c] = 0.0f;

        #pragma unroll
        for (int ks = 0; ks < KSTEPS; ++ks) {
            #pragma unroll
            for (int nb = 0; nb < 4; ++nb) {
                const uint2 b = *reinterpret_cast<const uint2*>(
                    bb + ((nb * KSTEPS + ks) * 32 + l) * 8);
                mma16832(acc[0][nb], a[0][ks], b.x, b.y);
                mma16832(acc[1][nb], a[1][ks], b.x, b.y);
            }
        }

        mbar_arrive(sbase + SM_MBE + cst * 8);

        const int cp = ck + PDIST;
        if (cp < NCHUNKS) {
            if (cp >= NSTAGE)
                mbar_wait_parity(sbase + SM_MBE + pst * 8, (uint32_t)pph);
            const char* src = reinterpret_cast<const char*>(g_Bfrag)
                              + cp * CHUNK_BYTES;
            const uint32_t dst = sbase + SM_BB + pst * CHUNK_BYTES;
            #pragma unroll
            for (int i = 0; i < 4; ++i) {
                const int off = (i * 128 + tid) * 16;
                cp16(dst + off, src + off);
            }
            cp_mbar_arrive_noinc(sbase + SM_MBF + pst * 8);
            if (++pst == NSTAGE) { pst = 0; pph ^= 1; }
        }

        // fold (csq - 2*dot) into running min
        #pragma unroll
        for (int nb = 0; nb < 4; ++nb) {
            const int col = ck * NCH + nb * 8 + 2 * t;
            const float cq0 = csq_s[col];
            const float cq1 = csq_s[col + 1];
            #pragma unroll
            for (int mt = 0; mt < 2; ++mt) {
                const float v0 = fminf(fmaf(-2.0f, acc[mt][nb][0], cq0),
                                       fmaf(-2.0f, acc[mt][nb][1], cq1));
                const float v1 = fminf(fmaf(-2.0f, acc[mt][nb][2], cq0),
                                       fmaf(-2.0f, acc[mt][nb][3], cq1));
                minv[mt][0] = fminf(minv[mt][0], v0);
                minv[mt][1] = fminf(minv[mt][1], v1);
            }
        }

        if (++cst == NSTAGE) { cst = 0; cph ^= 1; }
    }

    // ---- epilogue: per-row min -> sqrt -> deterministic partial sum ----
    float s = 0.0f;
    #pragma unroll
    for (int mt = 0; mt < 2; ++mt) {
        #pragma unroll
        for (int h = 0; h < 2; ++h) {
            float m = minv[mt][h];
            m = fminf(m, __shfl_xor_sync(0xFFFFFFFFu, m, 1));
            m = fminf(m, __shfl_xor_sync(0xFFFFFFFFu, m, 2));
            const float d = sqrtf(fmaxf(xs[mt][h] + m, 0.0f));
            if (t == 0) s += d;
        }
    }
    #pragma unroll
    for (int off = 16; off; off >>= 1) s += __shfl_down_sync(0xFFFFFFFFu, s, off);
    if (l == 0) red_s[w] = s;
    __syncthreads();

    __shared__ unsigned int is_last;
    if (tid == 0) {
        g_partials[blockIdx.x] = (red_s[0] + red_s[1]) + (red_s[2] + red_s[3]);
        __threadfence();
        const unsigned int prev = atomicAdd(&g_done, 1u);
        is_last = (prev == (unsigned)(NUM_CTAS - 1)) ? 1u : 0u;
    }
    __syncthreads();

    if (is_last) {
        __threadfence();
        float v = g_partials[tid] + g_partials[tid + 128]
                + g_partials[tid + 256] + g_partials[tid + 384];
        #pragma unroll
        for (int off = 16; off; off >>= 1) v += __shfl_down_sync(0xFFFFFFFFu, v, off);
        if (l == 0) red_s[w] = v;
        __syncthreads();
        if (tid == 0) {
            const float t2 = (red_s[0] + red_s[1]) + (red_s[2] + red_s[3]);
            out[0] = t2 * (ALPHA / (float)BATCH);
            g_done = 0u;                 // reset for next graph replay
            __threadfence();
        }
    }
}

} // namespace km

extern "C" void kernel_launch(void* const* d_in, const int* in_sizes, int n_in,
                              void* d_out, int out_size) {
    const float* emb = (const float*)d_in[0];   // [65536, 256] fp32
    const float* ctr = (const float*)d_in[1];   // [512, 256]  fp32
    float* out = (float*)d_out;                 // scalar fp32

    cudaFuncSetAttribute(km::kmeans_main,
                         cudaFuncAttributeMaxDynamicSharedMemorySize, km::SMEM_TOTAL);

    km::convert_centers<<<64, 32>>>(ctr);
    km::kmeans_main<<<km::NUM_CTAS, 128, km::SMEM_TOTAL>>>(emb, out);
}

// round 8
// speedup vs baseline: 1.0493x; 1.0493x over previous
#include <cuda_runtime.h>
#include <cuda_bf16.h>
#include <cstdint>
#include <cstddef>

// ============================================================================
// KMeansLoss on GB300 via legacy mma.sync (HMMA bf16) — harness ptxas target
// is sm_103 (no 'a'); tcgen05 unavailable. R8: R6 pipeline with N=64 chunks
// (8 chunks instead of 16): halves mbar/fold/loop overhead, 16 independent
// HMMA chains per k-step. FP8 (R7) proved the legacy path is FLOP-rate capped,
// so bf16 k16 is optimal per-FLOP; this round attacks the non-tensor overhead.
//
// loss = ALPHA * mean_n sqrt(max( xsq[n] + min_k( csq[k] - 2*dot(x_n,c_k) ), 0))
// ============================================================================

namespace km {

constexpr int BATCH = 65536;
constexpr int KC    = 512;
constexpr int DIM   = 256;
constexpr float ALPHA = 0.05f;

constexpr int M_CTA    = 128;
constexpr int NUM_CTAS = BATCH / M_CTA;     // 512
constexpr int NCH      = 64;                // centers per chunk
constexpr int NCHUNKS  = KC / NCH;          // 8
constexpr int NB       = NCH / 8;           // 8 n-blocks per chunk
constexpr int CHUNK_BYTES = NCH * DIM * 2;  // 32768
constexpr int NSTAGE   = 3;
constexpr int PDIST    = 2;

// ---- dynamic smem layout ----
constexpr int SM_CSQ  = 0;                  // 512 f = 2048 B
constexpr int SM_RED  = 2048;               // 4 f
constexpr int SM_MBF  = 2112;               // full mbars, 3 x 8B
constexpr int SM_MBE  = 2176;               // empty mbars, 3 x 8B
constexpr int SM_BB   = 4096;               // 3 x 32 KB B stages
constexpr int SMEM_TOTAL = SM_BB + NSTAGE * CHUNK_BYTES;   // 102400 (2 CTAs/SM)

// B fragments: [nbg(64)][ks(16)][lane(32)] x uint2 (b0 = k pair, b1 = k+8 pair)
__device__ uint2 g_Bfrag[(KC / 8) * 16 * 32];
__device__ float g_csq[KC];
__device__ float g_partials[NUM_CTAS];
__device__ unsigned int g_done;

// ---------------------------- helpers ---------------------------------------
__device__ __forceinline__ uint32_t pk_bf16x2(float lo, float hi) {
    uint32_t r;
    asm("cvt.rn.bf16x2.f32 %0, %1, %2;" : "=r"(r) : "f"(hi), "f"(lo));
    return r;
}
__device__ __forceinline__ void mma16816(float c[4], const uint32_t a[4],
                                         uint32_t b0, uint32_t b1) {
    asm volatile(
        "mma.sync.aligned.m16n8k16.row.col.f32.bf16.bf16.f32 "
        "{%0,%1,%2,%3}, {%4,%5,%6,%7}, {%8,%9}, {%0,%1,%2,%3};"
        : "+f"(c[0]), "+f"(c[1]), "+f"(c[2]), "+f"(c[3])
        : "r"(a[0]), "r"(a[1]), "r"(a[2]), "r"(a[3]), "r"(b0), "r"(b1));
}
__device__ __forceinline__ uint32_t smem_u32(const void* p) {
    return (uint32_t)__cvta_generic_to_shared(p);
}
__device__ __forceinline__ void cp16(uint32_t sdst, const void* gsrc) {
    asm volatile("cp.async.cg.shared.global [%0], [%1], 16;"
                 :: "r"(sdst), "l"(gsrc) : "memory");
}
__device__ __forceinline__ void cp_mbar_arrive_noinc(uint32_t mbar) {
    asm volatile("cp.async.mbarrier.arrive.noinc.shared::cta.b64 [%0];"
                 :: "r"(mbar) : "memory");
}
__device__ __forceinline__ void mbar_init(uint32_t a, uint32_t cnt) {
    asm volatile("mbarrier.init.shared.b64 [%0], %1;" :: "r"(a), "r"(cnt) : "memory");
}
__device__ __forceinline__ void mbar_arrive(uint32_t a) {
    asm volatile("mbarrier.arrive.shared.b64 _, [%0];" :: "r"(a) : "memory");
}
__device__ __forceinline__ void mbar_wait_parity(uint32_t mbar, uint32_t phase) {
    uint32_t done;
    do {
        asm volatile("{\n .reg .pred p;\n"
                     " mbarrier.try_wait.parity.acquire.cta.shared::cta.b64 p, [%1], %2, 0x989680;\n"
                     " selp.b32 %0, 1, 0, p;\n}"
                     : "=r"(done) : "r"(mbar), "r"(phase) : "memory");
    } while (!done);
}

// ------------------------- kernel 0: center convert -------------------------
__global__ void __launch_bounds__(32) convert_centers(const float* __restrict__ ctr) {
    const int l   = threadIdx.x & 31;
    const int nbg = blockIdx.x;                 // 0..63
    const int n   = nbg * 8 + (l >> 2);
    const float* row = ctr + (size_t)n * DIM;
    float cs = 0.0f;
    #pragma unroll
    for (int ks = 0; ks < 16; ++ks) {
        const int k0 = ks * 16 + 2 * (l & 3);
        const float2 v0 = *reinterpret_cast<const float2*>(row + k0);
        const float2 v1 = *reinterpret_cast<const float2*>(row + k0 + 8);
        cs = fmaf(v0.x, v0.x, cs); cs = fmaf(v0.y, v0.y, cs);
        cs = fmaf(v1.x, v1.x, cs); cs = fmaf(v1.y, v1.y, cs);
        uint2 u;
        u.x = pk_bf16x2(v0.x, v0.y);
        u.y = pk_bf16x2(v1.x, v1.y);
        g_Bfrag[(nbg * 16 + ks) * 32 + l] = u;
    }
    cs += __shfl_xor_sync(0xFFFFFFFFu, cs, 1);
    cs += __shfl_xor_sync(0xFFFFFFFFu, cs, 2);
    if ((l & 3) == 0) g_csq[n] = cs;
}

// ------------------------- kernel 1: main GEMM+min --------------------------
__global__ void __launch_bounds__(128, 2)
kmeans_main(const float* __restrict__ emb, float* __restrict__ out) {
    extern __shared__ char smem[];
    const int tid = threadIdx.x;
    const int w   = tid >> 5;        // warp 0..3
    const int l   = tid & 31;
    const int m0  = blockIdx.x * M_CTA;
    float* csq_s = reinterpret_cast<float*>(smem + SM_CSQ);
    float* red_s = reinterpret_cast<float*>(smem + SM_RED);
    const uint32_t sbase = smem_u32(smem);

    // ---- init pipeline mbarriers + stage csq in smem ----
    if (tid == 0) {
        #pragma unroll
        for (int s = 0; s < NSTAGE; ++s) {
            mbar_init(sbase + SM_MBF + s * 8, 128);
            mbar_init(sbase + SM_MBE + s * 8, 128);
        }
    }
    reinterpret_cast<float4*>(csq_s)[tid] =
        reinterpret_cast<const float4*>(g_csq)[tid];
    __syncthreads();

    // ---- prefill stages 0..PDIST-1 (16 cp16/thread per 32KB chunk) ----
    #pragma unroll
    for (int s = 0; s < PDIST; ++s) {
        const char* src = reinterpret_cast<const char*>(g_Bfrag) + s * CHUNK_BYTES;
        const uint32_t dst = sbase + SM_BB + s * CHUNK_BYTES;
        #pragma unroll
        for (int i = 0; i < 16; ++i) {
            const int off = (i * 128 + tid) * 16;
            cp16(dst + off, src + off);
        }
        cp_mbar_arrive_noinc(sbase + SM_MBF + s * 8);
    }

    // ---- A prologue: direct gmem -> register fragments, fused exact xsq ----
    uint32_t a[2][16][4];
    float xs[2][2];
    xs[0][0] = 0.0f; xs[0][1] = 0.0f; xs[1][0] = 0.0f; xs[1][1] = 0.0f;
    {
        const float* base = emb + (size_t)(m0 + w * 32 + (l >> 2)) * DIM + 2 * (l & 3);
        #pragma unroll
        for (int mt = 0; mt < 2; ++mt) {
            const float* p0 = base + (size_t)(mt * 16) * DIM;
            const float* p8 = p0 + (size_t)8 * DIM;
            #pragma unroll
            for (int ks = 0; ks < 16; ++ks) {
                const float2 v00 = *reinterpret_cast<const float2*>(p0 + ks * 16);
                const float2 v01 = *reinterpret_cast<const float2*>(p0 + ks * 16 + 8);
                const float2 v10 = *reinterpret_cast<const float2*>(p8 + ks * 16);
                const float2 v11 = *reinterpret_cast<const float2*>(p8 + ks * 16 + 8);
                xs[mt][0] = fmaf(v00.x, v00.x, xs[mt][0]);
                xs[mt][0] = fmaf(v00.y, v00.y, xs[mt][0]);
                xs[mt][0] = fmaf(v01.x, v01.x, xs[mt][0]);
                xs[mt][0] = fmaf(v01.y, v01.y, xs[mt][0]);
                xs[mt][1] = fmaf(v10.x, v10.x, xs[mt][1]);
                xs[mt][1] = fmaf(v10.y, v10.y, xs[mt][1]);
                xs[mt][1] = fmaf(v11.x, v11.x, xs[mt][1]);
                xs[mt][1] = fmaf(v11.y, v11.y, xs[mt][1]);
                a[mt][ks][0] = pk_bf16x2(v00.x, v00.y);
                a[mt][ks][1] = pk_bf16x2(v10.x, v10.y);
                a[mt][ks][2] = pk_bf16x2(v01.x, v01.y);
                a[mt][ks][3] = pk_bf16x2(v11.x, v11.y);
            }
        }
    }
    #pragma unroll
    for (int mt = 0; mt < 2; ++mt) {
        #pragma unroll
        for (int h = 0; h < 2; ++h) {
            xs[mt][h] += __shfl_xor_sync(0xFFFFFFFFu, xs[mt][h], 1);
            xs[mt][h] += __shfl_xor_sync(0xFFFFFFFFu, xs[mt][h], 2);
        }
    }

    float minv[2][2];
    minv[0][0] = 3.4e38f; minv[0][1] = 3.4e38f;
    minv[1][0] = 3.4e38f; minv[1][1] = 3.4e38f;

    // ---- mainloop: 8 chunks of 64 centers, mbarrier pipeline ----
    int cst = 0, cph = 0;
    int pst = PDIST, pph = 1;

    #pragma unroll 1
    for (int ck = 0; ck < NCHUNKS; ++ck) {
        mbar_wait_parity(sbase + SM_MBF + cst * 8, (uint32_t)cph);

        const char* bb = smem + SM_BB + cst * CHUNK_BYTES;

        float acc[2][NB][4];
        #pragma unroll
        for (int mt = 0; mt < 2; ++mt)
            #pragma unroll
            for (int nb = 0; nb < NB; ++nb)
                #pragma unroll
                for (int c = 0; c < 4; ++c) acc[mt][nb][c] = 0.0f;

        #pragma unroll
        for (int ks = 0; ks < 16; ++ks) {
            #pragma unroll
            for (int nb = 0; nb < NB; ++nb) {
                const uint2 b = *reinterpret_cast<const uint2*>(
                    bb + ((nb * 16 + ks) * 32 + l) * 8);
                mma16816(acc[0][nb], a[0][ks], b.x, b.y);
                mma16816(acc[1][nb], a[1][ks], b.x, b.y);
            }
        }

        mbar_arrive(sbase + SM_MBE + cst * 8);

        const int cp = ck + PDIST;
        if (cp < NCHUNKS) {
            if (cp >= NSTAGE)
                mbar_wait_parity(sbase + SM_MBE + pst * 8, (uint32_t)pph);
            const char* src = reinterpret_cast<const char*>(g_Bfrag)
                              + cp * CHUNK_BYTES;
            const uint32_t dst = sbase + SM_BB + pst * CHUNK_BYTES;
            #pragma unroll
            for (int i = 0; i < 16; ++i) {
                const int off = (i * 128 + tid) * 16;
                cp16(dst + off, src + off);
            }
            cp_mbar_arrive_noinc(sbase + SM_MBF + pst * 8);
            if (++pst == NSTAGE) { pst = 0; pph ^= 1; }
        }

        // fold (csq - 2*dot) into running min
        #pragma unroll
        for (int nb = 0; nb < NB; ++nb) {
            const int col = ck * NCH + nb * 8 + 2 * (l & 3);
            const float cq0 = csq_s[col];
            const float cq1 = csq_s[col + 1];
            #pragma unroll
            for (int mt = 0; mt < 2; ++mt) {
                const float v0 = fminf(fmaf(-2.0f, acc[mt][nb][0], cq0),
                                       fmaf(-2.0f, acc[mt][nb][1], cq1));
                const float v1 = fminf(fmaf(-2.0f, acc[mt][nb][2], cq0),
                                       fmaf(-2.0f, acc[mt][nb][3], cq1));
                minv[mt][0] = fminf(minv[mt][0], v0);
                minv[mt][1] = fminf(minv[mt][1], v1);
            }
        }

        if (++cst == NSTAGE) { cst = 0; cph ^= 1; }
    }

    // ---- epilogue: per-row min -> sqrt -> deterministic partial sum ----
    float s = 0.0f;
    #pragma unroll
    for (int mt = 0; mt < 2; ++mt) {
        #pragma unroll
        for (int h = 0; h < 2; ++h) {
            float m = minv[mt][h];
            m = fminf(m, __shfl_xor_sync(0xFFFFFFFFu, m, 1));
            m = fminf(m, __shfl_xor_sync(0xFFFFFFFFu, m, 2));
            const float d = sqrtf(fmaxf(xs[mt][h] + m, 0.0f));
            if ((l & 3) == 0) s += d;
        }
    }
    #pragma unroll
    for (int off = 16; off; off >>= 1) s += __shfl_down_sync(0xFFFFFFFFu, s, off);
    if (l == 0) red_s[w] = s;
    __syncthreads();

    __shared__ unsigned int is_last;
    if (tid == 0) {
        g_partials[blockIdx.x] = (red_s[0] + red_s[1]) + (red_s[2] + red_s[3]);
        __threadfence();
        const unsigned int prev = atomicAdd(&g_done, 1u);
        is_last = (prev == (unsigned)(NUM_CTAS - 1)) ? 1u : 0u;
    }
    __syncthreads();

    if (is_last) {
        __threadfence();
        float v = g_partials[tid] + g_partials[tid + 128]
                + g_partials[tid + 256] + g_partials[tid + 384];
        #pragma unroll
        for (int off = 16; off; off >>= 1) v += __shfl_down_sync(0xFFFFFFFFu, v, off);
        if (l == 0) red_s[w] = v;
        __syncthreads();
        if (tid == 0) {
            const float t = (red_s[0] + red_s[1]) + (red_s[2] + red_s[3]);
            out[0] = t * (ALPHA / (float)BATCH);
            g_done = 0u;                 // reset for next graph replay
            __threadfence();
        }
    }
}

} // namespace km

extern "C" void kernel_launch(void* const* d_in, const int* in_sizes, int n_in,
                              void* d_out, int out_size) {
    const float* emb = (const float*)d_in[0];   // [65536, 256] fp32
    const float* ctr = (const float*)d_in[1];   // [512, 256]  fp32
    float* out = (float*)d_out;                 // scalar fp32

    cudaFuncSetAttribute(km::kmeans_main,
                         cudaFuncAttributeMaxDynamicSharedMemorySize, km::SMEM_TOTAL);

    km::convert_centers<<<64, 32>>>(ctr);
    km::kmeans_main<<<km::NUM_CTAS, 128, km::SMEM_TOTAL>>>(emb, out);
}

// round 9
// speedup vs baseline: 1.1067x; 1.0546x over previous
#include <cuda_runtime.h>
#include <cuda_bf16.h>
#include <cstdint>
#include <cstddef>

// ============================================================================
// KMeansLoss on GB300 via legacy mma.sync (HMMA bf16) — harness ptxas target
// is sm_103 (no 'a'); tcgen05 unavailable.
//
// R9: 16 warps/SM experiment. 256-thread CTAs, each warp owns 16 rows
// (A = 64 regs), __launch_bounds__(256,2) -> 512 threads x <=128 regs = full
// RF, 16 warps/SM (2x R6). B fragments packed as uint4 (2 k-steps per
// LDS.128) to halve shared-load instruction count. Otherwise the proven R6
// free-running 6-stage mbarrier pipeline (N=32 chunks, PDIST=3).
//
// loss = ALPHA * mean_n sqrt(max( xsq[n] + min_k( csq[k] - 2*dot(x_n,c_k) ), 0))
// ============================================================================

namespace km {

constexpr int BATCH = 65536;
constexpr int KC    = 512;
constexpr int DIM   = 256;
constexpr float ALPHA = 0.05f;

constexpr int M_CTA    = 128;
constexpr int NUM_CTAS = BATCH / M_CTA;     // 512
constexpr int THREADS  = 256;               // 8 warps, 16 rows each
constexpr int NCH      = 32;                // centers per chunk
constexpr int NCHUNKS  = KC / NCH;          // 16
constexpr int CHUNK_BYTES = NCH * DIM * 2;  // 16384
constexpr int NSTAGE   = 6;
constexpr int PDIST    = 3;

// ---- dynamic smem layout ----
constexpr int SM_CSQ  = 0;                  // 512 f = 2048 B
constexpr int SM_RED  = 2048;               // 8 f
constexpr int SM_MBF  = 2112;               // full mbars, 6 x 8B
constexpr int SM_MBE  = 2176;               // empty mbars, 6 x 8B
constexpr int SM_BB   = 4096;               // 6 x 16 KB B stages
constexpr int SMEM_TOTAL = SM_BB + NSTAGE * CHUNK_BYTES;   // 102400 (2 CTAs/SM)

// B fragments, ks-paired: [nbg(64)][ksp(8)][lane(32)] x uint4
//   .x = b0(ks=2p), .y = b1(ks=2p), .z = b0(ks=2p+1), .w = b1(ks=2p+1)
__device__ uint4 g_Bfrag[(KC / 8) * 8 * 32];
__device__ float g_csq[KC];
__device__ float g_partials[NUM_CTAS];
__device__ unsigned int g_done;

// ---------------------------- helpers ---------------------------------------
__device__ __forceinline__ uint32_t pk_bf16x2(float lo, float hi) {
    uint32_t r;
    asm("cvt.rn.bf16x2.f32 %0, %1, %2;" : "=r"(r) : "f"(hi), "f"(lo));
    return r;
}
__device__ __forceinline__ void mma16816(float c[4], const uint32_t a[4],
                                         uint32_t b0, uint32_t b1) {
    asm volatile(
        "mma.sync.aligned.m16n8k16.row.col.f32.bf16.bf16.f32 "
        "{%0,%1,%2,%3}, {%4,%5,%6,%7}, {%8,%9}, {%0,%1,%2,%3};"
        : "+f"(c[0]), "+f"(c[1]), "+f"(c[2]), "+f"(c[3])
        : "r"(a[0]), "r"(a[1]), "r"(a[2]), "r"(a[3]), "r"(b0), "r"(b1));
}
__device__ __forceinline__ uint32_t smem_u32(const void* p) {
    return (uint32_t)__cvta_generic_to_shared(p);
}
__device__ __forceinline__ void cp16(uint32_t sdst, const void* gsrc) {
    asm volatile("cp.async.cg.shared.global [%0], [%1], 16;"
                 :: "r"(sdst), "l"(gsrc) : "memory");
}
__device__ __forceinline__ void cp_mbar_arrive_noinc(uint32_t mbar) {
    asm volatile("cp.async.mbarrier.arrive.noinc.shared::cta.b64 [%0];"
                 :: "r"(mbar) : "memory");
}
__device__ __forceinline__ void mbar_init(uint32_t a, uint32_t cnt) {
    asm volatile("mbarrier.init.shared.b64 [%0], %1;" :: "r"(a), "r"(cnt) : "memory");
}
__device__ __forceinline__ void mbar_arrive(uint32_t a) {
    asm volatile("mbarrier.arrive.shared.b64 _, [%0];" :: "r"(a) : "memory");
}
__device__ __forceinline__ void mbar_wait_parity(uint32_t mbar, uint32_t phase) {
    uint32_t done;
    do {
        asm volatile("{\n .reg .pred p;\n"
                     " mbarrier.try_wait.parity.acquire.cta.shared::cta.b64 p, [%1], %2, 0x989680;\n"
                     " selp.b32 %0, 1, 0, p;\n}"
                     : "=r"(done) : "r"(mbar), "r"(phase) : "memory");
    } while (!done);
}

// ------------------------- kernel 0: center convert -------------------------
// one warp per 8-center group; emits ks-paired uint4 fragments + exact csq.
__global__ void __launch_bounds__(32) convert_centers(const float* __restrict__ ctr) {
    const int l   = threadIdx.x & 31;
    const int nbg = blockIdx.x;                 // 0..63
    const int n   = nbg * 8 + (l >> 2);
    const float* row = ctr + (size_t)n * DIM;
    float cs = 0.0f;
    #pragma unroll
    for (int ksp = 0; ksp < 8; ++ksp) {
        uint4 u;
        #pragma unroll
        for (int j = 0; j < 2; ++j) {
            const int k0 = (ksp * 2 + j) * 16 + 2 * (l & 3);
            const float2 v0 = *reinterpret_cast<const float2*>(row + k0);
            const float2 v1 = *reinterpret_cast<const float2*>(row + k0 + 8);
            cs = fmaf(v0.x, v0.x, cs); cs = fmaf(v0.y, v0.y, cs);
            cs = fmaf(v1.x, v1.x, cs); cs = fmaf(v1.y, v1.y, cs);
            if (j == 0) { u.x = pk_bf16x2(v0.x, v0.y); u.y = pk_bf16x2(v1.x, v1.y); }
            else        { u.z = pk_bf16x2(v0.x, v0.y); u.w = pk_bf16x2(v1.x, v1.y); }
        }
        g_Bfrag[(nbg * 8 + ksp) * 32 + l] = u;
    }
    cs += __shfl_xor_sync(0xFFFFFFFFu, cs, 1);
    cs += __shfl_xor_sync(0xFFFFFFFFu, cs, 2);
    if ((l & 3) == 0) g_csq[n] = cs;
}

// ------------------------- kernel 1: main GEMM+min --------------------------
__global__ void __launch_bounds__(THREADS, 2)
kmeans_main(const float* __restrict__ emb, float* __restrict__ out) {
    extern __shared__ char smem[];
    const int tid = threadIdx.x;
    const int w   = tid >> 5;        // warp 0..7
    const int l   = tid & 31;
    const int m0  = blockIdx.x * M_CTA;
    float* csq_s = reinterpret_cast<float*>(smem + SM_CSQ);
    float* red_s = reinterpret_cast<float*>(smem + SM_RED);
    const uint32_t sbase = smem_u32(smem);

    // ---- init pipeline mbarriers + stage csq in smem ----
    if (tid == 0) {
        #pragma unroll
        for (int s = 0; s < NSTAGE; ++s) {
            mbar_init(sbase + SM_MBF + s * 8, THREADS);
            mbar_init(sbase + SM_MBE + s * 8, THREADS);
        }
    }
    if (tid < 128)
        reinterpret_cast<float4*>(csq_s)[tid] =
            reinterpret_cast<const float4*>(g_csq)[tid];
    __syncthreads();

    // ---- prefill stages 0..PDIST-1 (4 cp16/thread per 16KB chunk) ----
    #pragma unroll
    for (int s = 0; s < PDIST; ++s) {
        const char* src = reinterpret_cast<const char*>(g_Bfrag) + s * CHUNK_BYTES;
        const uint32_t dst = sbase + SM_BB + s * CHUNK_BYTES;
        #pragma unroll
        for (int i = 0; i < 4; ++i) {
            const int off = (i * THREADS + tid) * 16;
            cp16(dst + off, src + off);
        }
        cp_mbar_arrive_noinc(sbase + SM_MBF + s * 8);
    }

    // ---- A prologue: warp owns 16 rows; direct gmem -> 64 reg fragments ----
    uint32_t a[16][4];
    float xs0 = 0.0f, xs1 = 0.0f;
    {
        const float* p0 = emb + (size_t)(m0 + w * 16 + (l >> 2)) * DIM + 2 * (l & 3);
        const float* p8 = p0 + (size_t)8 * DIM;
        #pragma unroll
        for (int ks = 0; ks < 16; ++ks) {
            const float2 v00 = *reinterpret_cast<const float2*>(p0 + ks * 16);
            const float2 v01 = *reinterpret_cast<const float2*>(p0 + ks * 16 + 8);
            const float2 v10 = *reinterpret_cast<const float2*>(p8 + ks * 16);
            const float2 v11 = *reinterpret_cast<const float2*>(p8 + ks * 16 + 8);
            xs0 = fmaf(v00.x, v00.x, xs0); xs0 = fmaf(v00.y, v00.y, xs0);
            xs0 = fmaf(v01.x, v01.x, xs0); xs0 = fmaf(v01.y, v01.y, xs0);
            xs1 = fmaf(v10.x, v10.x, xs1); xs1 = fmaf(v10.y, v10.y, xs1);
            xs1 = fmaf(v11.x, v11.x, xs1); xs1 = fmaf(v11.y, v11.y, xs1);
            a[ks][0] = pk_bf16x2(v00.x, v00.y);
            a[ks][1] = pk_bf16x2(v10.x, v10.y);
            a[ks][2] = pk_bf16x2(v01.x, v01.y);
            a[ks][3] = pk_bf16x2(v11.x, v11.y);
        }
    }
    xs0 += __shfl_xor_sync(0xFFFFFFFFu, xs0, 1);
    xs0 += __shfl_xor_sync(0xFFFFFFFFu, xs0, 2);
    xs1 += __shfl_xor_sync(0xFFFFFFFFu, xs1, 1);
    xs1 += __shfl_xor_sync(0xFFFFFFFFu, xs1, 2);

    float minv0 = 3.4e38f, minv1 = 3.4e38f;

    // ---- mainloop: 16 chunks, mbarrier pipeline, no __syncthreads ----
    int cst = 0, cph = 0;
    int pst = PDIST, pph = 1;

    #pragma unroll 1
    for (int ck = 0; ck < NCHUNKS; ++ck) {
        mbar_wait_parity(sbase + SM_MBF + cst * 8, (uint32_t)cph);

        const char* bb = smem + SM_BB + cst * CHUNK_BYTES;

        float acc[4][4];
        #pragma unroll
        for (int nb = 0; nb < 4; ++nb)
            #pragma unroll
            for (int c = 0; c < 4; ++c) acc[nb][c] = 0.0f;

        #pragma unroll
        for (int ksp = 0; ksp < 8; ++ksp) {
            #pragma unroll
            for (int nb = 0; nb < 4; ++nb) {
                const uint4 b = *reinterpret_cast<const uint4*>(
                    bb + ((nb * 8 + ksp) * 32 + l) * 16);
                mma16816(acc[nb], a[2 * ksp],     b.x, b.y);
                mma16816(acc[nb], a[2 * ksp + 1], b.z, b.w);
            }
        }

        mbar_arrive(sbase + SM_MBE + cst * 8);

        const int cp = ck + PDIST;
        if (cp < NCHUNKS) {
            if (cp >= NSTAGE)
                mbar_wait_parity(sbase + SM_MBE + pst * 8, (uint32_t)pph);
            const char* src = reinterpret_cast<const char*>(g_Bfrag)
                              + cp * CHUNK_BYTES;
            const uint32_t dst = sbase + SM_BB + pst * CHUNK_BYTES;
            #pragma unroll
            for (int i = 0; i < 4; ++i) {
                const int off = (i * THREADS + tid) * 16;
                cp16(dst + off, src + off);
            }
            cp_mbar_arrive_noinc(sbase + SM_MBF + pst * 8);
            if (++pst == NSTAGE) { pst = 0; pph ^= 1; }
        }

        // fold (csq - 2*dot) into running min
        #pragma unroll
        for (int nb = 0; nb < 4; ++nb) {
            const int col = ck * NCH + nb * 8 + 2 * (l & 3);
            const float cq0 = csq_s[col];
            const float cq1 = csq_s[col + 1];
            const float v0 = fminf(fmaf(-2.0f, acc[nb][0], cq0),
                                   fmaf(-2.0f, acc[nb][1], cq1));
            const float v1 = fminf(fmaf(-2.0f, acc[nb][2], cq0),
                                   fmaf(-2.0f, acc[nb][3], cq1));
            minv0 = fminf(minv0, v0);
            minv1 = fminf(minv1, v1);
        }

        if (++cst == NSTAGE) { cst = 0; cph ^= 1; }
    }

    // ---- epilogue: per-row min -> sqrt -> deterministic partial sum ----
    minv0 = fminf(minv0, __shfl_xor_sync(0xFFFFFFFFu, minv0, 1));
    minv0 = fminf(minv0, __shfl_xor_sync(0xFFFFFFFFu, minv0, 2));
    minv1 = fminf(minv1, __shfl_xor_sync(0xFFFFFFFFu, minv1, 1));
    minv1 = fminf(minv1, __shfl_xor_sync(0xFFFFFFFFu, minv1, 2));
    float s = 0.0f;
    if ((l & 3) == 0)
        s = sqrtf(fmaxf(xs0 + minv0, 0.0f)) + sqrtf(fmaxf(xs1 + minv1, 0.0f));
    #pragma unroll
    for (int off = 16; off; off >>= 1) s += __shfl_down_sync(0xFFFFFFFFu, s, off);
    if (l == 0) red_s[w] = s;
    __syncthreads();

    __shared__ unsigned int is_last;
    if (tid == 0) {
        float t = 0.0f;
        #pragma unroll
        for (int i = 0; i < 8; ++i) t += red_s[i];
        g_partials[blockIdx.x] = t;
        __threadfence();
        const unsigned int prev = atomicAdd(&g_done, 1u);
        is_last = (prev == (unsigned)(NUM_CTAS - 1)) ? 1u : 0u;
    }
    __syncthreads();

    if (is_last) {
        __threadfence();
        float v = g_partials[tid] + g_partials[tid + 256];
        #pragma unroll
        for (int off = 16; off; off >>= 1) v += __shfl_down_sync(0xFFFFFFFFu, v, off);
        if (l == 0) red_s[w] = v;
        __syncthreads();
        if (tid == 0) {
            float t = 0.0f;
            #pragma unroll
            for (int i = 0; i < 8; ++i) t += red_s[i];
            out[0] = t * (ALPHA / (float)BATCH);
            g_done = 0u;                 // reset for next graph replay
            __threadfence();
        }
    }
}

} // namespace km

extern "C" void kernel_launch(void* const* d_in, const int* in_sizes, int n_in,
                              void* d_out, int out_size) {
    const float* emb = (const float*)d_in[0];   // [65536, 256] fp32
    const float* ctr = (const float*)d_in[1];   // [512, 256]  fp32
    float* out = (float*)d_out;                 // scalar fp32

    cudaFuncSetAttribute(km::kmeans_main,
                         cudaFuncAttributeMaxDynamicSharedMemorySize, km::SMEM_TOTAL);

    km::convert_centers<<<64, 32>>>(ctr);
    km::kmeans_main<<<km::NUM_CTAS, km::THREADS, km::SMEM_TOTAL>>>(emb, out);
}